// round 2
// baseline (speedup 1.0000x reference)
#include <cuda_runtime.h>
#include <math.h>

// Problem constants (fixed by the reference setup)
#define NPTS 8192
#define KNN 16
#define TS 2048          // candidates per smem tile
#define TPB 256          // threads per block (queries per block)

__device__ double g_acc;

__global__ void zero_acc_kernel() {
    g_acc = 0.0;
}

__global__ void finalize_kernel(float* out, int total_edges) {
    out[0] = (float)(g_acc / (double)total_edges);
}

__global__ __launch_bounds__(TPB)
void knn_loss_kernel(const float* __restrict__ pref,
                     const float* __restrict__ ppred) {
    __shared__ float sx[TS];
    __shared__ float sy[TS];
    __shared__ float sz[TS];
    __shared__ float warpsum[TPB / 32];

    const int blocks_per_batch = NPTS / TPB;   // 32
    const int b = blockIdx.x / blocks_per_batch;
    const int i = (blockIdx.x % blocks_per_batch) * TPB + threadIdx.x;

    const float* Pr = pref + (size_t)b * NPTS * 3;
    const float* Pp = ppred + (size_t)b * NPTS * 3;

    const float xi = Pr[i * 3 + 0];
    const float yi = Pr[i * 3 + 1];
    const float zi = Pr[i * 3 + 2];

    // top-K smallest squared distances (unsorted reservoir) + indices
    float bd[KNN];
    int   bi[KNN];
#pragma unroll
    for (int k = 0; k < KNN; k++) { bd[k] = 3.0e30f; bi[k] = -1; }
    float cmax = 3.0e30f;
    int   cpos = 0;

    for (int t0 = 0; t0 < NPTS; t0 += TS) {
        // coalesced tile load: 3*TS contiguous floats
        {
            const float* tilep = Pr + (size_t)t0 * 3;
            for (int idx = threadIdx.x; idx < 3 * TS; idx += TPB) {
                float v = tilep[idx];
                int j = idx / 3;
                int c = idx - j * 3;
                if (c == 0)      sx[j] = v;
                else if (c == 1) sy[j] = v;
                else             sz[j] = v;
            }
        }
        __syncthreads();

#pragma unroll 4
        for (int j = 0; j < TS; j++) {
            float dx = sx[j] - xi;
            float dy = sy[j] - yi;
            float dz = sz[j] - zi;
            float d2 = fmaf(dx, dx, fmaf(dy, dy, dz * dz));
            int gj = t0 + j;
            if (d2 < cmax && gj != i) {
                bd[cpos] = d2;
                bi[cpos] = gj;
                // rescan for new max
                float m = bd[0]; int p = 0;
#pragma unroll
                for (int k = 1; k < KNN; k++) {
                    if (bd[k] > m) { m = bd[k]; p = k; }
                }
                cmax = m; cpos = p;
            }
        }
        __syncthreads();
    }

    // epilogue: loss contribution for this query's K edges
    const float qx = Pp[i * 3 + 0];
    const float qy = Pp[i * 3 + 1];
    const float qz = Pp[i * 3 + 2];

    float s = 0.0f;
#pragma unroll
    for (int k = 0; k < KNN; k++) {
        int j = bi[k];
        float dr = sqrtf(bd[k]);
        float ex = Pp[j * 3 + 0] - qx;
        float ey = Pp[j * 3 + 1] - qy;
        float ez = Pp[j * 3 + 2] - qz;
        float dp = sqrtf(fmaf(ex, ex, fmaf(ey, ey, ez * ez)));
        s += fabsf(dr - dp);
    }

    // warp reduce
#pragma unroll
    for (int o = 16; o > 0; o >>= 1)
        s += __shfl_down_sync(0xFFFFFFFFu, s, o);

    const int lane = threadIdx.x & 31;
    const int wid  = threadIdx.x >> 5;
    if (lane == 0) warpsum[wid] = s;
    __syncthreads();
    if (threadIdx.x == 0) {
        float t = 0.0f;
#pragma unroll
        for (int w = 0; w < TPB / 32; w++) t += warpsum[w];
        atomicAdd(&g_acc, (double)t);
    }
}

extern "C" void kernel_launch(void* const* d_in, const int* in_sizes, int n_in,
                              void* d_out, int out_size) {
    const float* points_ref = (const float*)d_in[0];
    const float* points     = (const float*)d_in[1];
    float* out = (float*)d_out;

    const int B = in_sizes[0] / (NPTS * 3);      // 4
    const int total_edges = B * NPTS * KNN;      // 524288
    const int nblocks = B * (NPTS / TPB);        // 128

    zero_acc_kernel<<<1, 1>>>();
    knn_loss_kernel<<<nblocks, TPB>>>(points_ref, points);
    finalize_kernel<<<1, 1>>>(out, total_edges);
}